// round 7
// baseline (speedup 1.0000x reference)
#include <cuda_runtime.h>
#include <cstdint>

#define FM          14
#define HW          196           // 14*14
#define CH          2048
#define NCHUNK      16
#define CPC         (CH / NCHUNK)   // 128 channels per block
#define STAGE_CH    8
#define STAGE_FLTS  (STAGE_CH * HW)     // 1568 floats
#define STAGE_BYTES (STAGE_FLTS * 4)    // 6272 bytes (16B multiple)
#define NSTAGES     4
#define TOT_STAGES  (CPC / STAGE_CH)    // 16
#define NWIN        361
#define MAXB        64
#define NTHR        196

#define NEG_INF __int_as_float(0xff800000)

// Partial channel sums: [chunk][batch][hw]. Fully overwritten every run.
__device__ float g_part[NCHUNK * MAXB * HW];
// Per-batch arrival counters; reset by the finalizing block each run.
__device__ int g_count[MAXB];

// ---------------------------------------------------------------------------
// PTX helpers
// ---------------------------------------------------------------------------
__device__ __forceinline__ uint32_t smem_u32(const void* p) {
    return (uint32_t)__cvta_generic_to_shared(p);
}
__device__ __forceinline__ void mbar_init(uint32_t mbar, uint32_t count) {
    asm volatile("mbarrier.init.shared.b64 [%0], %1;" :: "r"(mbar), "r"(count) : "memory");
}
__device__ __forceinline__ void mbar_expect_tx(uint32_t mbar, uint32_t bytes) {
    asm volatile("mbarrier.arrive.expect_tx.shared.b64 _, [%0], %1;"
                 :: "r"(mbar), "r"(bytes) : "memory");
}
__device__ __forceinline__ void tma_bulk_g2s(uint32_t dst, const void* src,
                                             uint32_t bytes, uint32_t mbar) {
    asm volatile(
        "cp.async.bulk.shared::cta.global.mbarrier::complete_tx::bytes [%0], [%1], %2, [%3];"
        :: "r"(dst), "l"(src), "r"(bytes), "r"(mbar) : "memory");
}
__device__ __forceinline__ void mbar_wait(uint32_t mbar, uint32_t parity) {
    asm volatile(
        "{\n\t"
        ".reg .pred P;\n\t"
        "LAB_WAIT_%=:\n\t"
        "mbarrier.try_wait.parity.shared.b64 P, [%0], %1;\n\t"
        "@P bra LAB_DONE_%=;\n\t"
        "bra LAB_WAIT_%=;\n\t"
        "LAB_DONE_%=:\n\t"
        "}"
        :: "r"(mbar), "r"(parity) : "memory");
}
__device__ __forceinline__ void fence_proxy_async_cta() {
    asm volatile("fence.proxy.async.shared::cta;" ::: "memory");
}
__device__ __forceinline__ int atom_add_release_gpu(int* p, int v) {
    int old;
    asm volatile("atom.add.release.gpu.global.s32 %0, [%1], %2;"
                 : "=r"(old) : "l"(p), "r"(v) : "memory");
    return old;
}

__device__ __forceinline__ float pick4(const float a[4], int kk) {
    float r = a[0];
    if (kk == 1) r = a[1];
    if (kk == 2) r = a[2];
    if (kk == 3) r = a[3];
    return r;
}

// ---------------------------------------------------------------------------
// Single kernel. grid = (B, 16). Each block TMA-streams its 128-channel slice
// (100 KB) through a 4-deep SMEM ring and channel-sums it. Last block per
// batch (release-atomic arrival) runs the finalize.
// Output layout (fp32): [B*7 indices][B*7 window scores][B*361 all_scores]
// ---------------------------------------------------------------------------
__global__ __launch_bounds__(NTHR, 8) void appm_kernel(
    const float* __restrict__ x, const int* __restrict__ coords,
    float* __restrict__ out, int B)
{
    const int b     = blockIdx.x;
    const int chunk = blockIdx.y;
    const int tid   = threadIdx.x;   // 0..195

    __shared__ __align__(16) float    s_buf[NSTAGES * STAGE_FLTS];  // 25088 B
    __shared__ __align__(8)  uint64_t s_mbar[NSTAGES];
    __shared__ int s_last;

    const uint32_t buf_base  = smem_u32(s_buf);
    const uint32_t mbar_base = smem_u32(s_mbar);

    if (tid == 0) {
#pragma unroll
        for (int s = 0; s < NSTAGES; s++) mbar_init(mbar_base + s * 8, 1);
        fence_proxy_async_cta();
    }
    __syncthreads();

    // ---- Phase 1: TMA-staged channel-sum ----------------------------------
    const float* src_base = x + ((size_t)b * CH + (size_t)chunk * CPC) * HW;

    if (tid == 0) {
#pragma unroll
        for (int s = 0; s < NSTAGES; s++) {
            uint32_t mb = mbar_base + s * 8;
            mbar_expect_tx(mb, STAGE_BYTES);
            tma_bulk_g2s(buf_base + s * STAGE_BYTES,
                         src_base + s * STAGE_FLTS, STAGE_BYTES, mb);
        }
    }

    float acc = 0.f;
#pragma unroll 4
    for (int i = 0; i < TOT_STAGES; i++) {
        const int slot = i % NSTAGES;
        const uint32_t parity = (uint32_t)((i / NSTAGES) & 1);
        mbar_wait(mbar_base + slot * 8, parity);

        const float* st = s_buf + slot * STAGE_FLTS;
#pragma unroll
        for (int r = 0; r < STAGE_CH; r++) acc += st[r * HW + tid];

        __syncthreads();   // everyone done with this slot before refill
        if (tid == 0 && i + NSTAGES < TOT_STAGES) {
            fence_proxy_async_cta();
            uint32_t mb = mbar_base + slot * 8;
            mbar_expect_tx(mb, STAGE_BYTES);
            tma_bulk_g2s(buf_base + slot * STAGE_BYTES,
                         src_base + (size_t)(i + NSTAGES) * STAGE_FLTS,
                         STAGE_BYTES, mb);
        }
    }

    g_part[(chunk * B + b) * HW + tid] = acc;

    // ---- Arrival: last block for this batch runs the epilogue -------------
    __syncthreads();
    if (tid == 0) {
        int old = atom_add_release_gpu(&g_count[b], 1);
        s_last = (old == NCHUNK - 1);
    }
    __syncthreads();
    if (!s_last) return;
    if (tid == 0) g_count[b] = 0;   // reset for next graph replay

    // ---- Phase 2: finalize (aliases the dead staging buffer) --------------
    float* ssum    = s_buf;            // 196
    float* scores  = s_buf + 256;      // 361
    float* cbox    = s_buf + 768;      // 1444
    int*   sel_idx = (int*)(s_buf + 2304);  // 7
    float* sel_sc  = s_buf + 2320;          // 7

    for (int i = tid; i < NWIN * 4; i += NTHR) cbox[i] = (float)coords[i];

    {
        float s = 0.f;
#pragma unroll
        for (int k = 0; k < NCHUNK; k++) s += __ldcg(&g_part[(k * B + b) * HW + tid]);
        ssum[tid] = s;
    }
    __syncthreads();

    float* all_scores_out = out + 14 * B;   // after indices[B*7] + scores[B*7]
    for (int w = tid; w < NWIN; w += NTHR) {
        int i, j, rh, rw;
        if (w < 121)      { rh = 4; rw = 4; int l = w;       i = l / 11; j = l % 11; }
        else if (w < 241) { rh = 3; rw = 5; int l = w - 121; i = l / 10; j = l % 10; }
        else              { rh = 5; rw = 3; int l = w - 241; i = l / 12; j = l % 12; }
        float s = 0.f;
        for (int di = 0; di < rh; di++)
            for (int dj = 0; dj < rw; dj++)
                s += ssum[(i + di) * FM + (j + dj)];
        s /= (float)(rh * rw);
        scores[w] = s;
        all_scores_out[b * NWIN + w] = s;
    }
    __syncthreads();

    // ---- Phase 3: greedy NMS, warp g handles group g ----------------------
    const int wid  = tid >> 5;
    const int lane = tid & 31;
    if (wid < 3) {
        const int starts[3] = {0, 121, 241};
        const int counts[3] = {121, 120, 120};
        const int ns[3]     = {2, 3, 2};
        const int outoff[3] = {0, 2, 5};
        const float thresh  = 0.25f;

        const int st  = starts[wid];
        const int cnt = counts[wid];
        const int n   = ns[wid];

        float sc[4], x0[4], y0[4], x1[4], y1[4];
        bool  alive[4];
#pragma unroll
        for (int k = 0; k < 4; k++) {
            int ii = k * 32 + lane;
            bool valid = (ii < cnt);
            alive[k] = valid;
            int gi = st + (valid ? ii : 0);
            sc[k] = valid ? scores[gi] : 0.f;
            x0[k] = cbox[gi * 4 + 0];
            y0[k] = cbox[gi * 4 + 1];
            x1[k] = cbox[gi * 4 + 2];
            y1[k] = cbox[gi * 4 + 3];
        }

        for (int step = 0; step < n; step++) {
            float bv = NEG_INF;
            int   bi = 0x7FFFFFFF;
#pragma unroll
            for (int k = 0; k < 4; k++) {
                float vkv = alive[k] ? sc[k] : NEG_INF;
                int   vki = k * 32 + lane;
                if (vki < cnt && (vkv > bv || (vkv == bv && vki < bi))) { bv = vkv; bi = vki; }
            }
#pragma unroll
            for (int off = 16; off > 0; off >>= 1) {
                float ov = __shfl_down_sync(0xFFFFFFFFu, bv, off);
                int   oi = __shfl_down_sync(0xFFFFFFFFu, bi, off);
                if (ov > bv || (ov == bv && oi < bi)) { bv = ov; bi = oi; }
            }
            bi = __shfl_sync(0xFFFFFFFFu, bi, 0);

            if (lane == 0) {
                sel_idx[outoff[wid] + step] = st + bi;
                sel_sc [outoff[wid] + step] = scores[st + bi];
            }

            const int kk = bi >> 5;
            const int srcLane = bi & 31;
            float BX0 = __shfl_sync(0xFFFFFFFFu, pick4(x0, kk), srcLane);
            float BY0 = __shfl_sync(0xFFFFFFFFu, pick4(y0, kk), srcLane);
            float BX1 = __shfl_sync(0xFFFFFFFFu, pick4(x1, kk), srcLane);
            float BY1 = __shfl_sync(0xFFFFFFFFu, pick4(y1, kk), srcLane);
            float areaB = (BX1 - BX0) * (BY1 - BY0);

#pragma unroll
            for (int k = 0; k < 4; k++) {
                float ix0 = fmaxf(BX0, x0[k]);
                float iy0 = fmaxf(BY0, y0[k]);
                float ix1 = fminf(BX1, x1[k]);
                float iy1 = fminf(BY1, y1[k]);
                float inter = fmaxf(ix1 - ix0, 0.f) * fmaxf(iy1 - iy0, 0.f);
                float areaK = (x1[k] - x0[k]) * (y1[k] - y0[k]);
                float iou = inter / (areaB + areaK - inter);
                if (!(iou < thresh)) alive[k] = false;
            }
        }
    }
    __syncthreads();

    if (tid < 7) {
        out[b * 7 + tid]         = (float)sel_idx[tid];
        out[7 * B + b * 7 + tid] = sel_sc[tid];
    }
}

extern "C" void kernel_launch(void* const* d_in, const int* in_sizes, int n_in,
                              void* d_out, int out_size) {
    const float* x      = (const float*)d_in[0];
    const int*   coords = (const int*)d_in[1];
    float*       out    = (float*)d_out;

    const int B = in_sizes[0] / (CH * HW);   // 64

    dim3 grid(B, NCHUNK);
    appm_kernel<<<grid, NTHR>>>(x, coords, out, B);
}

// round 8
// speedup vs baseline: 1.1641x; 1.1641x over previous
#include <cuda_runtime.h>
#include <cstdint>

#define FM      14
#define HW      196          // 14*14
#define CH      2048
#define CHUNKS  16
#define CPC     (CH / CHUNKS)   // 128 channels per chunk
#define NWIN    361
#define MAXB    64
#define NTHR    196

#define NEG_INF __int_as_float(0xff800000)

// Partial channel sums: [chunk][batch][hw]. Fully overwritten every run.
__device__ float g_part[CHUNKS * MAXB * HW];
// Per-batch arrival counters; reset by the finalizing block each run.
__device__ int g_count[MAXB];

__device__ __forceinline__ int atom_add_release_gpu(int* p, int v) {
    int old;
    asm volatile("atom.add.release.gpu.global.s32 %0, [%1], %2;"
                 : "=r"(old) : "l"(p), "r"(v) : "memory");
    return old;
}

__device__ __forceinline__ float pick4(const float a[4], int kk) {
    float r = a[0];
    if (kk == 1) r = a[1];
    if (kk == 2) r = a[2];
    if (kk == 3) r = a[3];
    return r;
}

// ---------------------------------------------------------------------------
// Fused kernel. grid = (B, 16). Each block LDG-streams its 128-channel slice
// (unroll 8 -> MLP_p1=8), writes a partial, release-arrives; the last block
// per batch runs the finalize (L2-hot __ldcg gather, windows, NMS, outputs).
// __launch_bounds__(196, 7): 46-reg budget keeps 7 blocks (43 warps)/SM with
// the 8-deep float4 load batch intact. No gpu-scope fences anywhere.
// Output layout (fp32): [B*7 indices][B*7 window scores][B*361 all_scores]
// ---------------------------------------------------------------------------
__global__ __launch_bounds__(NTHR, 7) void appm_kernel(
    const float* __restrict__ x, const int* __restrict__ coords,
    float* __restrict__ out, int B)
{
    const int b     = blockIdx.x;
    const int chunk = blockIdx.y;
    const int tid   = threadIdx.x;          // 0..195
    const int grp   = tid / 49;             // 0..3
    const int v     = tid - grp * 49;       // 0..48

    __shared__ float4 red[4 * 49];
    __shared__ int    s_last;

    // ---- Phase 1: channel-sum this (batch, chunk) slice, unroll 8 ---------
    const float4* base = reinterpret_cast<const float4*>(
        x + ((size_t)b * CH + (size_t)chunk * CPC) * HW);

    float4 acc = make_float4(0.f, 0.f, 0.f, 0.f);
#pragma unroll 8
    for (int c = grp; c < CPC; c += 4) {
        float4 t = base[c * 49 + v];
        acc.x += t.x; acc.y += t.y; acc.z += t.z; acc.w += t.w;
    }
    red[grp * 49 + v] = acc;
    __syncthreads();

    if (tid < HW) {
        const float* rf = reinterpret_cast<const float*>(red);
        g_part[(chunk * B + b) * HW + tid] =
            rf[tid] + rf[HW + tid] + rf[2 * HW + tid] + rf[3 * HW + tid];
    }

    // ---- Arrival: last block for this batch runs the epilogue -------------
    __syncthreads();
    if (tid == 0) {
        int old = atom_add_release_gpu(&g_count[b], 1);
        s_last = (old == CHUNKS - 1);
    }
    __syncthreads();
    if (!s_last) return;
    if (tid == 0) g_count[b] = 0;   // reset for next graph replay

    // ---- Phase 2: finalize (cold path, once per batch) --------------------
    __shared__ float ssum[HW];
    __shared__ float scores[NWIN];
    __shared__ float cbox[NWIN * 4];
    __shared__ int   sel_idx[7];
    __shared__ float sel_sc[7];

    for (int i = tid; i < NWIN * 4; i += NTHR) cbox[i] = (float)coords[i];

    {
        float s = 0.f;
#pragma unroll
        for (int k = 0; k < CHUNKS; k++) s += __ldcg(&g_part[(k * B + b) * HW + tid]);
        ssum[tid] = s;
    }
    __syncthreads();

    float* all_scores_out = out + 14 * B;   // after indices[B*7] + scores[B*7]
    for (int w = tid; w < NWIN; w += NTHR) {
        int i, j, rh, rw;
        if (w < 121)      { rh = 4; rw = 4; int l = w;       i = l / 11; j = l % 11; }
        else if (w < 241) { rh = 3; rw = 5; int l = w - 121; i = l / 10; j = l % 10; }
        else              { rh = 5; rw = 3; int l = w - 241; i = l / 12; j = l % 12; }
        float s = 0.f;
        for (int di = 0; di < rh; di++)
            for (int dj = 0; dj < rw; dj++)
                s += ssum[(i + di) * FM + (j + dj)];
        s /= (float)(rh * rw);
        scores[w] = s;
        all_scores_out[b * NWIN + w] = s;
    }
    __syncthreads();

    // ---- Phase 3: greedy NMS, warp g handles group g ----------------------
    const int wid  = tid >> 5;
    const int lane = tid & 31;
    if (wid < 3) {
        const int starts[3] = {0, 121, 241};
        const int counts[3] = {121, 120, 120};
        const int ns[3]     = {2, 3, 2};
        const int outoff[3] = {0, 2, 5};
        const float thresh  = 0.25f;

        const int st  = starts[wid];
        const int cnt = counts[wid];
        const int n   = ns[wid];

        float sc[4], x0[4], y0[4], x1[4], y1[4];
        bool  alive[4];
#pragma unroll
        for (int k = 0; k < 4; k++) {
            int ii = k * 32 + lane;
            bool valid = (ii < cnt);
            alive[k] = valid;
            int gi = st + (valid ? ii : 0);
            sc[k] = valid ? scores[gi] : 0.f;
            x0[k] = cbox[gi * 4 + 0];
            y0[k] = cbox[gi * 4 + 1];
            x1[k] = cbox[gi * 4 + 2];
            y1[k] = cbox[gi * 4 + 3];
        }

        for (int step = 0; step < n; step++) {
            float bv = NEG_INF;
            int   bi = 0x7FFFFFFF;
#pragma unroll
            for (int k = 0; k < 4; k++) {
                float vkv = alive[k] ? sc[k] : NEG_INF;
                int   vki = k * 32 + lane;
                if (vki < cnt && (vkv > bv || (vkv == bv && vki < bi))) { bv = vkv; bi = vki; }
            }
#pragma unroll
            for (int off = 16; off > 0; off >>= 1) {
                float ov = __shfl_down_sync(0xFFFFFFFFu, bv, off);
                int   oi = __shfl_down_sync(0xFFFFFFFFu, bi, off);
                if (ov > bv || (ov == bv && oi < bi)) { bv = ov; bi = oi; }
            }
            bi = __shfl_sync(0xFFFFFFFFu, bi, 0);

            if (lane == 0) {
                sel_idx[outoff[wid] + step] = st + bi;
                sel_sc [outoff[wid] + step] = scores[st + bi];
            }

            const int kk = bi >> 5;
            const int srcLane = bi & 31;
            float BX0 = __shfl_sync(0xFFFFFFFFu, pick4(x0, kk), srcLane);
            float BY0 = __shfl_sync(0xFFFFFFFFu, pick4(y0, kk), srcLane);
            float BX1 = __shfl_sync(0xFFFFFFFFu, pick4(x1, kk), srcLane);
            float BY1 = __shfl_sync(0xFFFFFFFFu, pick4(y1, kk), srcLane);
            float areaB = (BX1 - BX0) * (BY1 - BY0);

#pragma unroll
            for (int k = 0; k < 4; k++) {
                float ix0 = fmaxf(BX0, x0[k]);
                float iy0 = fmaxf(BY0, y0[k]);
                float ix1 = fminf(BX1, x1[k]);
                float iy1 = fminf(BY1, y1[k]);
                float inter = fmaxf(ix1 - ix0, 0.f) * fmaxf(iy1 - iy0, 0.f);
                float areaK = (x1[k] - x0[k]) * (y1[k] - y0[k]);
                float iou = inter / (areaB + areaK - inter);
                if (!(iou < thresh)) alive[k] = false;
            }
        }
    }
    __syncthreads();

    if (tid < 7) {
        out[b * 7 + tid]         = (float)sel_idx[tid];
        out[7 * B + b * 7 + tid] = sel_sc[tid];
    }
}

extern "C" void kernel_launch(void* const* d_in, const int* in_sizes, int n_in,
                              void* d_out, int out_size) {
    const float* x      = (const float*)d_in[0];
    const int*   coords = (const int*)d_in[1];
    float*       out    = (float*)d_out;

    const int B = in_sizes[0] / (CH * HW);   // 64

    dim3 grid(B, CHUNKS);
    appm_kernel<<<grid, NTHR>>>(x, coords, out, B);
}

// round 9
// speedup vs baseline: 1.3448x; 1.1552x over previous
#include <cuda_runtime.h>
#include <cstdint>

#define FM      14
#define HW      196          // 14*14
#define CH      2048
#define CHUNKS  16
#define CPC     (CH / CHUNKS)   // 128 channels per chunk
#define NWIN    361
#define MAXB    64

#define NEG_INF __int_as_float(0xff800000)

// Partial channel sums: [chunk][batch][hw]. Fully overwritten every run.
__device__ float g_part[CHUNKS * MAXB * HW];
// Per-batch arrival counters. Zero at load; reset by consumer each run.
__device__ int g_count[MAXB];

__device__ __forceinline__ int atom_add_release_gpu(int* p, int v) {
    int old;
    asm volatile("atom.add.release.gpu.global.s32 %0, [%1], %2;"
                 : "=r"(old) : "l"(p), "r"(v) : "memory");
    return old;
}
__device__ __forceinline__ int ld_acquire_gpu(const int* p) {
    int v;
    asm volatile("ld.acquire.gpu.global.s32 %0, [%1];" : "=r"(v) : "l"(p) : "memory");
    return v;
}

__device__ __forceinline__ float pick4(const float a[4], int kk) {
    float r = a[0];
    if (kk == 1) r = a[1];
    if (kk == 2) r = a[2];
    if (kk == 3) r = a[3];
    return r;
}

// ---------------------------------------------------------------------------
// Kernel 1: lean streaming reduction (identical to the 22.6us version) plus
// a PDL trigger at block start and one release-atomic arrival at block end.
// ---------------------------------------------------------------------------
__global__ __launch_bounds__(196) void chan_sum_kernel(const float* __restrict__ x, int B) {
    // Allow the dependent (finalize) kernel to start scheduling as soon as
    // all our blocks have launched; it spins on per-batch counters.
    asm volatile("griddepcontrol.launch_dependents;" ::: "memory");

    const int b     = blockIdx.x;
    const int chunk = blockIdx.y;
    const int tid   = threadIdx.x;          // 0..195
    const int grp   = tid / 49;             // 0..3
    const int v     = tid - grp * 49;       // 0..48

    const float4* base = reinterpret_cast<const float4*>(
        x + ((size_t)b * CH + (size_t)chunk * CPC) * HW);

    float4 acc = make_float4(0.f, 0.f, 0.f, 0.f);
#pragma unroll 8
    for (int c = grp; c < CPC; c += 4) {
        float4 t = base[c * 49 + v];
        acc.x += t.x; acc.y += t.y; acc.z += t.z; acc.w += t.w;
    }

    __shared__ float4 red[4 * 49];
    red[grp * 49 + v] = acc;
    __syncthreads();

    if (tid < HW) {
        const float* rf = reinterpret_cast<const float*>(red);
        g_part[(chunk * B + b) * HW + tid] =
            rf[tid] + rf[HW + tid] + rf[2 * HW + tid] + rf[3 * HW + tid];
    }
    __syncthreads();
    if (tid == 0) (void)atom_add_release_gpu(&g_count[b], 1);
}

// ---------------------------------------------------------------------------
// Kernel 2: finalize. One block per batch; spins until its batch's 16 chunk
// partials have arrived (overlapped with kernel 1's tail under PDL), then
// sums partials, computes window scores, greedy NMS, writes outputs.
// Output layout (fp32): [B*7 indices][B*7 window scores][B*361 all_scores]
// ---------------------------------------------------------------------------
__global__ __launch_bounds__(384) void appm_finalize_kernel(
    const int* __restrict__ coords, float* __restrict__ out, int B)
{
    const int b   = blockIdx.x;
    const int tid = threadIdx.x;

    __shared__ float ssum[HW];
    __shared__ float scores[NWIN];
    __shared__ float cbox[NWIN * 4];
    __shared__ int   sel_idx[7];
    __shared__ float sel_sc[7];

    // Prologue overlaps with the spin: load coordinates.
    for (int i = tid; i < NWIN * 4; i += blockDim.x) cbox[i] = (float)coords[i];

    // Wait for this batch's 16 chunk partials.
    if (tid == 0) {
        while (ld_acquire_gpu(&g_count[b]) < CHUNKS) __nanosleep(32);
        g_count[b] = 0;   // reset for next graph replay
    }
    __syncthreads();

    if (tid < HW) {
        float s = 0.f;
#pragma unroll
        for (int k = 0; k < CHUNKS; k++) s += __ldcg(&g_part[(k * B + b) * HW + tid]);
        ssum[tid] = s;
    }
    __syncthreads();

    float* all_scores_out = out + 14 * B;   // after indices[B*7] + scores[B*7]
    for (int w = tid; w < NWIN; w += blockDim.x) {
        int i, j, rh, rw;
        if (w < 121)      { rh = 4; rw = 4; int l = w;       i = l / 11; j = l % 11; }
        else if (w < 241) { rh = 3; rw = 5; int l = w - 121; i = l / 10; j = l % 10; }
        else              { rh = 5; rw = 3; int l = w - 241; i = l / 12; j = l % 12; }
        float s = 0.f;
        for (int di = 0; di < rh; di++)
            for (int dj = 0; dj < rw; dj++)
                s += ssum[(i + di) * FM + (j + dj)];
        s /= (float)(rh * rw);
        scores[w] = s;
        all_scores_out[b * NWIN + w] = s;
    }
    __syncthreads();

    const int wid  = tid >> 5;
    const int lane = tid & 31;
    if (wid < 3) {
        const int starts[3] = {0, 121, 241};
        const int counts[3] = {121, 120, 120};
        const int ns[3]     = {2, 3, 2};
        const int outoff[3] = {0, 2, 5};
        const float thresh  = 0.25f;

        const int st  = starts[wid];
        const int cnt = counts[wid];
        const int n   = ns[wid];

        float sc[4], x0[4], y0[4], x1[4], y1[4];
        bool  alive[4];
#pragma unroll
        for (int k = 0; k < 4; k++) {
            int ii = k * 32 + lane;
            bool valid = (ii < cnt);
            alive[k] = valid;
            int gi = st + (valid ? ii : 0);
            sc[k] = valid ? scores[gi] : 0.f;
            x0[k] = cbox[gi * 4 + 0];
            y0[k] = cbox[gi * 4 + 1];
            x1[k] = cbox[gi * 4 + 2];
            y1[k] = cbox[gi * 4 + 3];
        }

        for (int step = 0; step < n; step++) {
            float bv = NEG_INF;
            int   bi = 0x7FFFFFFF;
#pragma unroll
            for (int k = 0; k < 4; k++) {
                float vkv = alive[k] ? sc[k] : NEG_INF;
                int   vki = k * 32 + lane;
                if (vki < cnt && (vkv > bv || (vkv == bv && vki < bi))) { bv = vkv; bi = vki; }
            }
#pragma unroll
            for (int off = 16; off > 0; off >>= 1) {
                float ov = __shfl_down_sync(0xFFFFFFFFu, bv, off);
                int   oi = __shfl_down_sync(0xFFFFFFFFu, bi, off);
                if (ov > bv || (ov == bv && oi < bi)) { bv = ov; bi = oi; }
            }
            bi = __shfl_sync(0xFFFFFFFFu, bi, 0);

            if (lane == 0) {
                sel_idx[outoff[wid] + step] = st + bi;
                sel_sc [outoff[wid] + step] = scores[st + bi];
            }

            const int kk = bi >> 5;
            const int srcLane = bi & 31;
            float BX0 = __shfl_sync(0xFFFFFFFFu, pick4(x0, kk), srcLane);
            float BY0 = __shfl_sync(0xFFFFFFFFu, pick4(y0, kk), srcLane);
            float BX1 = __shfl_sync(0xFFFFFFFFu, pick4(x1, kk), srcLane);
            float BY1 = __shfl_sync(0xFFFFFFFFu, pick4(y1, kk), srcLane);
            float areaB = (BX1 - BX0) * (BY1 - BY0);

#pragma unroll
            for (int k = 0; k < 4; k++) {
                float ix0 = fmaxf(BX0, x0[k]);
                float iy0 = fmaxf(BY0, y0[k]);
                float ix1 = fminf(BX1, x1[k]);
                float iy1 = fminf(BY1, y1[k]);
                float inter = fmaxf(ix1 - ix0, 0.f) * fmaxf(iy1 - iy0, 0.f);
                float areaK = (x1[k] - x0[k]) * (y1[k] - y0[k]);
                float iou = inter / (areaB + areaK - inter);
                if (!(iou < thresh)) alive[k] = false;
            }
        }
    }
    __syncthreads();

    if (tid < 7) {
        out[b * 7 + tid]         = (float)sel_idx[tid];
        out[7 * B + b * 7 + tid] = sel_sc[tid];
    }
}

extern "C" void kernel_launch(void* const* d_in, const int* in_sizes, int n_in,
                              void* d_out, int out_size) {
    const float* x      = (const float*)d_in[0];
    const int*   coords = (const int*)d_in[1];
    float*       out    = (float*)d_out;

    const int B = in_sizes[0] / (CH * HW);   // 64

    dim3 grid1(B, CHUNKS);
    chan_sum_kernel<<<grid1, 196>>>(x, B);

    // Finalize kernel with Programmatic Dependent Launch so it can co-schedule
    // with kernel 1's draining wave; falls back to a plain launch on error.
    cudaLaunchConfig_t cfg = {};
    cfg.gridDim  = dim3(B, 1, 1);
    cfg.blockDim = dim3(384, 1, 1);
    cfg.dynamicSmemBytes = 0;
    cfg.stream = 0;
    cudaLaunchAttribute attrs[1];
    attrs[0].id = cudaLaunchAttributeProgrammaticStreamSerialization;
    attrs[0].val.programmaticStreamSerializationAllowed = 1;
    cfg.attrs = attrs;
    cfg.numAttrs = 1;

    cudaError_t err = cudaLaunchKernelEx(&cfg, appm_finalize_kernel, coords, out, B);
    if (err != cudaSuccess) {
        (void)cudaGetLastError();   // clear
        appm_finalize_kernel<<<B, 384>>>(coords, out, B);
    }
}